// round 16
// baseline (speedup 1.0000x reference)
#include <cuda_runtime.h>
#include <cuda_fp16.h>
#include <cstdint>

#define N_NODES 50000
#define D_IN    128
#define D_H     128
#define D_Z2    64
#define D_Z     32
#define MAX_E   800000
#define CSR_BLOCKS 148

// -------- device scratch --------
__device__ __align__(16) float  d_dinv[N_NODES];
__device__ __align__(16) int    d_cnt [N_NODES];      // self-zeroing
__device__ __align__(16) int    d_cur [N_NODES + 4];
__device__ __align__(16) int    d_rs  [N_NODES + 4];
__device__ __align__(16) int    d_part[64];
__device__ __align__(16) int    d_csr [MAX_E];
__device__ __align__(16) __half d_g1  [N_NODES * D_H];   // h0 = x@W1, fp16 gather source
__device__ __align__(16) float  d_h   [N_NODES * D_H];   // layer-1 output (fp32)
__device__ __align__(16) __half d_g2  [N_NODES * D_Z2];  // (h@[Wmu|Wls])*dinv, fp16

// grid barrier state (g_gen monotone across graph replays -> replay-safe)
__device__ int      g_bar = 0;
__device__ unsigned g_gen = 0;

// -------- helpers --------
__device__ __forceinline__ uint32_t tf32_hi(float x) {
    uint32_t u;
    asm("cvt.rna.tf32.f32 %0, %1;" : "=r"(u) : "f"(x));
    return u;
}
__device__ __forceinline__ void tf32_split(float x, uint32_t& hi, uint32_t& lo) {
    hi = tf32_hi(x);
    lo = tf32_hi(x - __uint_as_float(hi));
}
__device__ __forceinline__ void mma_tf32(float c[4], const uint32_t a[4], const uint32_t b[2]) {
    asm volatile(
        "mma.sync.aligned.m16n8k8.row.col.f32.tf32.tf32.f32 "
        "{%0,%1,%2,%3}, {%4,%5,%6,%7}, {%8,%9}, {%0,%1,%2,%3};"
        : "+f"(c[0]), "+f"(c[1]), "+f"(c[2]), "+f"(c[3])
        : "r"(a[0]), "r"(a[1]), "r"(a[2]), "r"(a[3]), "r"(b[0]), "r"(b[1]));
}
__device__ __forceinline__ float4 h4_to_f4(uint2 v) {
    float2 fa = __half22float2(*reinterpret_cast<__half2*>(&v.x));
    float2 fb = __half22float2(*reinterpret_cast<__half2*>(&v.y));
    return make_float4(fa.x, fa.y, fb.x, fb.y);
}

__device__ __forceinline__ void grid_barrier() {
    __syncthreads();
    __threadfence();
    if (threadIdx.x == 0) {
        unsigned my = *((volatile unsigned*)&g_gen);   // read BEFORE arriving
        if (atomicAdd(&g_bar, 1) == (int)gridDim.x - 1) {
            g_bar = 0;
            __threadfence();
            atomicAdd(&g_gen, 1u);
        } else {
            while (*((volatile unsigned*)&g_gen) == my) { }
        }
    }
    __syncthreads();
}

// ==================== fused CSR build: hist -> scan -> scatter ====================
__global__ __launch_bounds__(256) void csr_build_kernel(
    const int* __restrict__ src1, const int* __restrict__ dst1, int E1,
    const int* __restrict__ src2, const int* __restrict__ dst2, int E2,
    int* __restrict__ cnt, int* __restrict__ part,
    int* __restrict__ rs, int* __restrict__ cur,
    float* __restrict__ dinv, int* __restrict__ csr, int n, int nchunk)
{
    __shared__ int sh[256];
    __shared__ int base_s;
    const int tid = threadIdx.x;
    const int nq1 = E1 >> 2, nq2 = E2 >> 2, nq = nq1 + nq2;
    const int gsz = gridDim.x * blockDim.x;

    // ---- phase 1: histogram ----
    for (int i = blockIdx.x * blockDim.x + tid; i < nq; i += gsz) {
        int4 d = (i < nq1) ? *reinterpret_cast<const int4*>(dst1 + i * 4)
                           : *reinterpret_cast<const int4*>(dst2 + (i - nq1) * 4);
        atomicAdd(&cnt[d.x], 1);
        atomicAdd(&cnt[d.y], 1);
        atomicAdd(&cnt[d.z], 1);
        atomicAdd(&cnt[d.w], 1);
    }
    grid_barrier();

    // ---- phase 2a: per-chunk partial sums (chunks of 1024 nodes) ----
    if (blockIdx.x < (unsigned)nchunk) {
        int i = blockIdx.x * 1024 + tid * 4;
        int s = 0;
        if (i < n) {
            int4 v = *reinterpret_cast<const int4*>(cnt + i);
            s = v.x + v.y + v.z + v.w;
        }
        sh[tid] = s;
        __syncthreads();
        for (int off = 128; off > 0; off >>= 1) {
            if (tid < off) sh[tid] += sh[tid + off];
            __syncthreads();
        }
        if (tid == 0) part[blockIdx.x] = sh[0];
    }
    grid_barrier();

    // ---- phase 2b: exclusive scan + write rs/cur/dinv, zero cnt ----
    if (blockIdx.x < (unsigned)nchunk) {
        int b = blockIdx.x;
        if (tid == 0) {
            int base = 0;
            for (int j = 0; j < b; j++) base += part[j];
            base_s = base;
            if (b == 0) {
                int tot = 0;
                for (int j = 0; j < nchunk; j++) tot += part[j];
                rs[n] = tot;
            }
        }
        int i = b * 1024 + tid * 4;
        int4 v = make_int4(0, 0, 0, 0);
        if (i < n) v = *reinterpret_cast<const int4*>(cnt + i);
        int s = v.x + v.y + v.z + v.w;
        sh[tid] = s;
        __syncthreads();
        for (int off = 1; off < 256; off <<= 1) {
            int tmp = (tid >= off) ? sh[tid - off] : 0;
            __syncthreads();
            sh[tid] += tmp;
            __syncthreads();
        }
        int thrbase = base_s + sh[tid] - s;
        if (i < n) {
            int r0 = thrbase;
            rs[i]     = r0; cur[i]     = r0; dinv[i]     = rsqrtf((float)(v.x + 1));
            int r1 = r0 + v.x;
            rs[i + 1] = r1; cur[i + 1] = r1; dinv[i + 1] = rsqrtf((float)(v.y + 1));
            int r2 = r1 + v.y;
            rs[i + 2] = r2; cur[i + 2] = r2; dinv[i + 2] = rsqrtf((float)(v.z + 1));
            int r3 = r2 + v.z;
            rs[i + 3] = r3; cur[i + 3] = r3; dinv[i + 3] = rsqrtf((float)(v.w + 1));
            *reinterpret_cast<int4*>(cnt + i) = make_int4(0, 0, 0, 0);
        }
    }
    grid_barrier();

    // ---- phase 3: scatter ----
    for (int i = blockIdx.x * blockDim.x + tid; i < nq; i += gsz) {
        int4 s4, d4;
        if (i < nq1) {
            s4 = *reinterpret_cast<const int4*>(src1 + i * 4);
            d4 = *reinterpret_cast<const int4*>(dst1 + i * 4);
        } else {
            s4 = *reinterpret_cast<const int4*>(src2 + (i - nq1) * 4);
            d4 = *reinterpret_cast<const int4*>(dst2 + (i - nq1) * 4);
        }
        csr[atomicAdd(&cur[d4.x], 1)] = s4.x;
        csr[atomicAdd(&cur[d4.y], 1)] = s4.y;
        csr[atomicAdd(&cur[d4.z], 1)] = s4.z;
        csr[atomicAdd(&cur[d4.w], 1)] = s4.w;
    }
}

// ==================== GEMM1: 3xTF32, h0 = x@W1 -> fp16 ====================
__global__ __launch_bounds__(256) void mma_gemm1_kernel(
    const float* __restrict__ X, const float* __restrict__ W,
    __half* __restrict__ g, int nrows)
{
    constexpr int NOUT = 128;
    constexpr int WN = 64, NT = 8, LDA = 36;
    __shared__ float As[128 * LDA];
    __shared__ float Bs[NOUT * LDA];

    const int tid = threadIdx.x;
    const int wid = tid >> 5, lane = tid & 31;
    const int wm = wid & 3, wn = wid >> 2;
    const int row0 = blockIdx.x * 128;
    const int qid = lane >> 2, qt = lane & 3;

    float acc[2][NT][4];
#pragma unroll
    for (int mi = 0; mi < 2; mi++)
#pragma unroll
        for (int ni = 0; ni < NT; ni++)
#pragma unroll
            for (int j = 0; j < 4; j++) acc[mi][ni][j] = 0.0f;

    for (int c = 0; c < 4; c++) {
#pragma unroll
        for (int i = tid; i < 1024; i += 256) {
            int r = i >> 3, c4 = (i & 7) * 4;
            float4 v = make_float4(0.f, 0.f, 0.f, 0.f);
            if (row0 + r < nrows)
                v = *reinterpret_cast<const float4*>(X + (size_t)(row0 + r) * 128 + c * 32 + c4);
            *reinterpret_cast<float4*>(&As[r * LDA + c4]) = v;
        }
#pragma unroll
        for (int i = tid; i < NOUT * 32; i += 256) {
            int nn = i % NOUT, kk = i / NOUT;
            Bs[nn * LDA + kk] = W[(size_t)(c * 32 + kk) * NOUT + nn];
        }
        __syncthreads();

#pragma unroll
        for (int ks = 0; ks < 4; ks++) {
            uint32_t ahi[2][4], alo[2][4];
#pragma unroll
            for (int mi = 0; mi < 2; mi++) {
                int r = wm * 32 + mi * 16 + qid;
                int k = ks * 8 + qt;
                tf32_split(As[r * LDA + k],           ahi[mi][0], alo[mi][0]);
                tf32_split(As[(r + 8) * LDA + k],     ahi[mi][1], alo[mi][1]);
                tf32_split(As[r * LDA + k + 4],       ahi[mi][2], alo[mi][2]);
                tf32_split(As[(r + 8) * LDA + k + 4], ahi[mi][3], alo[mi][3]);
            }
#pragma unroll
            for (int ni = 0; ni < NT; ni++) {
                int nn = wn * WN + ni * 8 + qid;
                int k = ks * 8 + qt;
                uint32_t bhi[2], blo[2];
                tf32_split(Bs[nn * LDA + k],     bhi[0], blo[0]);
                tf32_split(Bs[nn * LDA + k + 4], bhi[1], blo[1]);
#pragma unroll
                for (int mi = 0; mi < 2; mi++) {
                    mma_tf32(acc[mi][ni], ahi[mi], blo);
                    mma_tf32(acc[mi][ni], alo[mi], bhi);
                    mma_tf32(acc[mi][ni], ahi[mi], bhi);
                }
            }
        }
        __syncthreads();
    }

#pragma unroll
    for (int mi = 0; mi < 2; mi++) {
        int r0 = row0 + wm * 32 + mi * 16 + qid;
        int r1 = r0 + 8;
#pragma unroll
        for (int ni = 0; ni < NT; ni++) {
            int col = wn * WN + ni * 8 + qt * 2;
            if (r0 < nrows)
                *reinterpret_cast<__half2*>(g + (size_t)r0 * NOUT + col) =
                    __floats2half2_rn(acc[mi][ni][0], acc[mi][ni][1]);
            if (r1 < nrows)
                *reinterpret_cast<__half2*>(g + (size_t)r1 * NOUT + col) =
                    __floats2half2_rn(acc[mi][ni][2], acc[mi][ni][3]);
        }
    }
}

// ==================== GEMM2: 1xTF32, g2 = (h@[Wmu|Wls]) * dinv -> fp16 ====================
__global__ __launch_bounds__(256) void mma_gemm2_kernel(
    const float* __restrict__ X, const float* __restrict__ Wmu, const float* __restrict__ Wls,
    const float* __restrict__ dinv, __half* __restrict__ g, int nrows)
{
    constexpr int NOUT = 64;
    constexpr int WN = 32, NT = 4, LDA = 36;
    __shared__ float As[128 * LDA];
    __shared__ float Bs[NOUT * LDA];

    const int tid = threadIdx.x;
    const int wid = tid >> 5, lane = tid & 31;
    const int wm = wid & 3, wn = wid >> 2;
    const int row0 = blockIdx.x * 128;
    const int qid = lane >> 2, qt = lane & 3;

    float acc[2][NT][4];
#pragma unroll
    for (int mi = 0; mi < 2; mi++)
#pragma unroll
        for (int ni = 0; ni < NT; ni++)
#pragma unroll
            for (int j = 0; j < 4; j++) acc[mi][ni][j] = 0.0f;

    for (int c = 0; c < 4; c++) {
#pragma unroll
        for (int i = tid; i < 1024; i += 256) {
            int r = i >> 3, c4 = (i & 7) * 4;
            float4 v = make_float4(0.f, 0.f, 0.f, 0.f);
            if (row0 + r < nrows)
                v = *reinterpret_cast<const float4*>(X + (size_t)(row0 + r) * 128 + c * 32 + c4);
            *reinterpret_cast<float4*>(&As[r * LDA + c4]) = v;
        }
#pragma unroll
        for (int i = tid; i < NOUT * 32; i += 256) {
            int nn = i % NOUT, kk = i / NOUT;
            int krow = c * 32 + kk;
            Bs[nn * LDA + kk] = (nn < D_Z) ? Wmu[(size_t)krow * D_Z + nn]
                                           : Wls[(size_t)krow * D_Z + (nn - D_Z)];
        }
        __syncthreads();

#pragma unroll
        for (int ks = 0; ks < 4; ks++) {
            uint32_t a[2][4];
#pragma unroll
            for (int mi = 0; mi < 2; mi++) {
                int r = wm * 32 + mi * 16 + qid;
                int k = ks * 8 + qt;
                a[mi][0] = tf32_hi(As[r * LDA + k]);
                a[mi][1] = tf32_hi(As[(r + 8) * LDA + k]);
                a[mi][2] = tf32_hi(As[r * LDA + k + 4]);
                a[mi][3] = tf32_hi(As[(r + 8) * LDA + k + 4]);
            }
#pragma unroll
            for (int ni = 0; ni < NT; ni++) {
                int nn = wn * WN + ni * 8 + qid;
                int k = ks * 8 + qt;
                uint32_t b[2];
                b[0] = tf32_hi(Bs[nn * LDA + k]);
                b[1] = tf32_hi(Bs[nn * LDA + k + 4]);
#pragma unroll
                for (int mi = 0; mi < 2; mi++)
                    mma_tf32(acc[mi][ni], a[mi], b);
            }
        }
        __syncthreads();
    }

#pragma unroll
    for (int mi = 0; mi < 2; mi++) {
        int r0 = row0 + wm * 32 + mi * 16 + qid;
        int r1 = r0 + 8;
        float w0 = (r0 < nrows) ? dinv[r0] : 0.f;
        float w1 = (r1 < nrows) ? dinv[r1] : 0.f;
#pragma unroll
        for (int ni = 0; ni < NT; ni++) {
            int col = wn * WN + ni * 8 + qt * 2;
            if (r0 < nrows)
                *reinterpret_cast<__half2*>(g + (size_t)r0 * NOUT + col) =
                    __floats2half2_rn(acc[mi][ni][0] * w0, acc[mi][ni][1] * w0);
            if (r1 < nrows)
                *reinterpret_cast<__half2*>(g + (size_t)r1 * NOUT + col) =
                    __floats2half2_rn(acc[mi][ni][2] * w1, acc[mi][ni][3] * w1);
        }
    }
}

// -------- agg1 (F=128, fp16 source): h[d] = relu( wd*(Σ dinv[s]*h0[s] + wd*h0[d]) + b ) --------
__global__ __launch_bounds__(256) void agg1_kernel(
    const int* __restrict__ rs, const int* __restrict__ csr,
    const __half* __restrict__ h0, const float* __restrict__ dinv,
    const float* __restrict__ b1, float* __restrict__ h, int n)
{
    int d = (blockIdx.x * blockDim.x + threadIdx.x) >> 5;
    int lane = threadIdx.x & 31;
    if (d >= n) return;

    const uint2* gv = reinterpret_cast<const uint2*>(h0);
    float wd = dinv[d];
    float4 sv = h4_to_f4(gv[(size_t)d * 32 + lane]);
    float4 a0 = make_float4(sv.x * wd, sv.y * wd, sv.z * wd, sv.w * wd);
    float4 a1 = make_float4(0.f, 0.f, 0.f, 0.f);
    float4 a2 = make_float4(0.f, 0.f, 0.f, 0.f);
    float4 a3 = make_float4(0.f, 0.f, 0.f, 0.f);

    int e = rs[d], end = rs[d + 1];
    for (; e + 4 <= end; e += 4) {
        int s0 = __ldg(&csr[e]);
        int s1 = __ldg(&csr[e + 1]);
        int s2 = __ldg(&csr[e + 2]);
        int s3 = __ldg(&csr[e + 3]);
        float w0 = __ldg(&dinv[s0]);
        float w1 = __ldg(&dinv[s1]);
        float w2 = __ldg(&dinv[s2]);
        float w3 = __ldg(&dinv[s3]);
        float4 v0 = h4_to_f4(gv[(size_t)s0 * 32 + lane]);
        float4 v1 = h4_to_f4(gv[(size_t)s1 * 32 + lane]);
        float4 v2 = h4_to_f4(gv[(size_t)s2 * 32 + lane]);
        float4 v3 = h4_to_f4(gv[(size_t)s3 * 32 + lane]);
        a0.x = fmaf(v0.x, w0, a0.x); a0.y = fmaf(v0.y, w0, a0.y);
        a0.z = fmaf(v0.z, w0, a0.z); a0.w = fmaf(v0.w, w0, a0.w);
        a1.x = fmaf(v1.x, w1, a1.x); a1.y = fmaf(v1.y, w1, a1.y);
        a1.z = fmaf(v1.z, w1, a1.z); a1.w = fmaf(v1.w, w1, a1.w);
        a2.x = fmaf(v2.x, w2, a2.x); a2.y = fmaf(v2.y, w2, a2.y);
        a2.z = fmaf(v2.z, w2, a2.z); a2.w = fmaf(v2.w, w2, a2.w);
        a3.x = fmaf(v3.x, w3, a3.x); a3.y = fmaf(v3.y, w3, a3.y);
        a3.z = fmaf(v3.z, w3, a3.z); a3.w = fmaf(v3.w, w3, a3.w);
    }
    for (; e < end; e++) {
        int s0 = __ldg(&csr[e]);
        float w0 = __ldg(&dinv[s0]);
        float4 v0 = h4_to_f4(gv[(size_t)s0 * 32 + lane]);
        a0.x = fmaf(v0.x, w0, a0.x); a0.y = fmaf(v0.y, w0, a0.y);
        a0.z = fmaf(v0.z, w0, a0.z); a0.w = fmaf(v0.w, w0, a0.w);
    }
    float4 bb = reinterpret_cast<const float4*>(b1)[lane];
    float sx = (a0.x + a1.x) + (a2.x + a3.x);
    float sy = (a0.y + a1.y) + (a2.y + a3.y);
    float sz = (a0.z + a1.z) + (a2.z + a3.z);
    float sw = (a0.w + a1.w) + (a2.w + a3.w);
    float4 r;
    r.x = fmaxf(fmaf(sx, wd, bb.x), 0.f);
    r.y = fmaxf(fmaf(sy, wd, bb.y), 0.f);
    r.z = fmaxf(fmaf(sz, wd, bb.z), 0.f);
    r.w = fmaxf(fmaf(sw, wd, bb.w), 0.f);
    reinterpret_cast<float4*>(h)[(size_t)d * 32 + lane] = r;
}

// -------- agg2 (F=64, fp16 source): fused bias + mu/logstd split --------
__global__ __launch_bounds__(256) void agg2_kernel(
    const int* __restrict__ rs, const int* __restrict__ csr,
    const __half* __restrict__ g, const float* __restrict__ dinv,
    const float* __restrict__ bmu, const float* __restrict__ bls,
    float* __restrict__ out, int n)
{
    int d = (blockIdx.x * blockDim.x + threadIdx.x) >> 5;
    int lane = threadIdx.x & 31;
    if (d >= n) return;

    const __half2* gv = reinterpret_cast<const __half2*>(g);
    float2 a0 = __half22float2(gv[(size_t)d * 32 + lane]);
    float2 a1 = make_float2(0.f, 0.f);
    float2 a2 = make_float2(0.f, 0.f);
    float2 a3 = make_float2(0.f, 0.f);

    int e = rs[d], end = rs[d + 1];
    for (; e + 4 <= end; e += 4) {
        int s0 = __ldg(&csr[e]);
        int s1 = __ldg(&csr[e + 1]);
        int s2 = __ldg(&csr[e + 2]);
        int s3 = __ldg(&csr[e + 3]);
        float2 v0 = __half22float2(gv[(size_t)s0 * 32 + lane]);
        float2 v1 = __half22float2(gv[(size_t)s1 * 32 + lane]);
        float2 v2 = __half22float2(gv[(size_t)s2 * 32 + lane]);
        float2 v3 = __half22float2(gv[(size_t)s3 * 32 + lane]);
        a0.x += v0.x; a0.y += v0.y;
        a1.x += v1.x; a1.y += v1.y;
        a2.x += v2.x; a2.y += v2.y;
        a3.x += v3.x; a3.y += v3.y;
    }
    for (; e < end; e++) {
        int s0 = __ldg(&csr[e]);
        float2 v0 = __half22float2(gv[(size_t)s0 * 32 + lane]);
        a0.x += v0.x; a0.y += v0.y;
    }
    float w = dinv[d];
    float vx = ((a0.x + a1.x) + (a2.x + a3.x)) * w;
    float vy = ((a0.y + a1.y) + (a2.y + a3.y)) * w;
    int c0 = lane * 2, c1 = lane * 2 + 1;
    if (c0 < D_Z) {
        float2 o = make_float2(vx + bmu[c0], vy + bmu[c1]);
        reinterpret_cast<float2*>(out)[(size_t)d * 16 + lane] = o;
    } else {
        float2 o = make_float2(vx + bls[c0 - D_Z], vy + bls[c1 - D_Z]);
        reinterpret_cast<float2*>(out + (size_t)n * D_Z)[(size_t)d * 16 + (lane - 16)] = o;
    }
}

extern "C" void kernel_launch(void* const* d_in, const int* in_sizes, int n_in,
                              void* d_out, int out_size)
{
    const float* x    = (const float*)d_in[0];
    const int*   ei1  = (const int*)d_in[1];
    const int*   ei2  = (const int*)d_in[2];
    const float* W1   = (const float*)d_in[3];
    const float* b1   = (const float*)d_in[4];
    const float* Wmu  = (const float*)d_in[5];
    const float* bmu  = (const float*)d_in[6];
    const float* Wls  = (const float*)d_in[7];
    const float* bls  = (const float*)d_in[8];
    float* out = (float*)d_out;

    static cudaStream_t sB = nullptr;
    static cudaEvent_t evFork = nullptr, evJoin = nullptr;
    if (sB == nullptr) {
        cudaStreamCreateWithFlags(&sB, cudaStreamNonBlocking);
        cudaEventCreateWithFlags(&evFork, cudaEventDisableTiming);
        cudaEventCreateWithFlags(&evJoin, cudaEventDisableTiming);
    }

    float *p_dinv, *p_h;
    __half *p_g1, *p_g2;
    int *p_cnt, *p_cur, *p_rs, *p_part, *p_csr;
    cudaGetSymbolAddress((void**)&p_dinv, d_dinv);
    cudaGetSymbolAddress((void**)&p_cnt,  d_cnt);
    cudaGetSymbolAddress((void**)&p_cur,  d_cur);
    cudaGetSymbolAddress((void**)&p_rs,   d_rs);
    cudaGetSymbolAddress((void**)&p_part, d_part);
    cudaGetSymbolAddress((void**)&p_csr,  d_csr);
    cudaGetSymbolAddress((void**)&p_g1,   d_g1);
    cudaGetSymbolAddress((void**)&p_h,    d_h);
    cudaGetSymbolAddress((void**)&p_g2,   d_g2);

    const int n  = in_sizes[0] / D_IN;   // 50000
    const int E1 = in_sizes[1] / 2;      // 600000
    const int E2 = in_sizes[2] / 2;      // 200000
    const int* src1 = ei1; const int* dst1 = ei1 + E1;
    const int* src2 = ei2; const int* dst2 = ei2 + E2;

    const int T = 256;
    const int tiles = (n + 127) / 128;        // 391
    const int nchunk = (n + 1023) / 1024;     // 49

    // ---- fork: GEMM1 concurrent with fused CSR build ----
    cudaEventRecord(evFork, 0);
    cudaStreamWaitEvent(sB, evFork, 0);
    mma_gemm1_kernel<<<tiles, 256, 0, sB>>>(x, W1, p_g1, n);
    cudaEventRecord(evJoin, sB);

    // ---- fused CSR build (1 node: hist -> scan -> scatter via grid barriers) ----
    csr_build_kernel<<<CSR_BLOCKS, 256>>>(src1, dst1, E1, src2, dst2, E2,
                                          p_cnt, p_part, p_rs, p_cur, p_dinv, p_csr,
                                          n, nchunk);

    // ---- join, then layer-1 aggregation ----
    cudaStreamWaitEvent(0, evJoin, 0);
    agg1_kernel<<<(n * 32 + T - 1) / T, T>>>(p_rs, p_csr, p_g1, p_dinv, b1, p_h, n);

    // ---- layer 2 (fused heads, 1xTF32) ----
    mma_gemm2_kernel<<<tiles, 256>>>(p_h, Wmu, Wls, p_dinv, p_g2, n);
    agg2_kernel<<<(n * 32 + T - 1) / T, T>>>(p_rs, p_csr, p_g2, p_dinv, bmu, bls, out, n);
}

// round 17
// speedup vs baseline: 1.5181x; 1.5181x over previous
#include <cuda_runtime.h>
#include <cuda_fp16.h>
#include <cstdint>

#define N_NODES 50000
#define D_IN    128
#define D_H     128
#define D_Z2    64
#define D_Z     32
#define MAX_E   800000

// -------- device scratch --------
__device__ __align__(16) float  d_dinv[N_NODES];
__device__ __align__(16) int    d_cnt [N_NODES];      // self-zeroing
__device__ __align__(16) int    d_cur [N_NODES + 4];
__device__ __align__(16) int    d_rs  [N_NODES + 4];
__device__ __align__(16) int    d_part[64];
__device__ __align__(16) int    d_csr [MAX_E];
__device__ __align__(16) __half d_g1  [N_NODES * D_H];   // h0 = x@W1, fp16
__device__ __align__(16) __half d_h   [N_NODES * D_H];   // layer-1 output, fp16
__device__ __align__(16) __half d_g2  [N_NODES * D_Z2];  // (h@[Wmu|Wls])*dinv, fp16

// -------- helpers --------
__device__ __forceinline__ void mma_f16(float c[4], const uint32_t a[4], const uint32_t b[2]) {
    asm volatile(
        "mma.sync.aligned.m16n8k16.row.col.f32.f16.f16.f32 "
        "{%0,%1,%2,%3}, {%4,%5,%6,%7}, {%8,%9}, {%0,%1,%2,%3};"
        : "+f"(c[0]), "+f"(c[1]), "+f"(c[2]), "+f"(c[3])
        : "r"(a[0]), "r"(a[1]), "r"(a[2]), "r"(a[3]), "r"(b[0]), "r"(b[1]));
}
__device__ __forceinline__ float4 h4_to_f4(uint2 v) {
    float2 fa = __half22float2(*reinterpret_cast<__half2*>(&v.x));
    float2 fb = __half22float2(*reinterpret_cast<__half2*>(&v.y));
    return make_float4(fa.x, fa.y, fb.x, fb.y);
}

// -------- CSR build (R14 form: 4 short kernels) --------
__global__ void hist2_kernel(int* __restrict__ cnt,
                             const int* __restrict__ dst1, int E1,
                             const int* __restrict__ dst2, int E2) {
    int q1 = E1 >> 2, q2 = E2 >> 2;
    int i = blockIdx.x * blockDim.x + threadIdx.x;
    int4 d;
    if (i < q1)            d = *reinterpret_cast<const int4*>(dst1 + i * 4);
    else if (i < q1 + q2)  d = *reinterpret_cast<const int4*>(dst2 + (i - q1) * 4);
    else return;
    atomicAdd(&cnt[d.x], 1);
    atomicAdd(&cnt[d.y], 1);
    atomicAdd(&cnt[d.z], 1);
    atomicAdd(&cnt[d.w], 1);
}

__global__ void partial_kernel(const int* __restrict__ cnt, int* __restrict__ part, int n) {
    __shared__ int sh[256];
    int t = threadIdx.x;
    int i = blockIdx.x * 1024 + t * 4;
    int s = 0;
    if (i < n) {
        int4 v = *reinterpret_cast<const int4*>(cnt + i);
        s = v.x + v.y + v.z + v.w;
    }
    sh[t] = s;
    __syncthreads();
    for (int off = 128; off > 0; off >>= 1) {
        if (t < off) sh[t] += sh[t + off];
        __syncthreads();
    }
    if (t == 0) part[blockIdx.x] = sh[0];
}

__global__ void scan_write_kernel(int* __restrict__ cnt, const int* __restrict__ part,
                                  int* __restrict__ rs, int* __restrict__ cur,
                                  float* __restrict__ dinv, int n, int nblk) {
    __shared__ int sh[256];
    __shared__ int base_s;
    int t = threadIdx.x;
    int b = blockIdx.x;
    if (t == 0) {
        int base = 0;
        for (int j = 0; j < b; j++) base += part[j];
        base_s = base;
        if (b == 0) {
            int tot = 0;
            for (int j = 0; j < nblk; j++) tot += part[j];
            rs[n] = tot;
        }
    }
    int i = b * 1024 + t * 4;
    int4 v = make_int4(0, 0, 0, 0);
    if (i < n) v = *reinterpret_cast<const int4*>(cnt + i);
    int s = v.x + v.y + v.z + v.w;
    sh[t] = s;
    __syncthreads();
    for (int off = 1; off < 256; off <<= 1) {
        int tmp = (t >= off) ? sh[t - off] : 0;
        __syncthreads();
        sh[t] += tmp;
        __syncthreads();
    }
    int thrbase = base_s + sh[t] - s;
    if (i < n) {
        int r0 = thrbase;
        rs[i]     = r0; cur[i]     = r0; dinv[i]     = rsqrtf((float)(v.x + 1));
        int r1 = r0 + v.x;
        rs[i + 1] = r1; cur[i + 1] = r1; dinv[i + 1] = rsqrtf((float)(v.y + 1));
        int r2 = r1 + v.y;
        rs[i + 2] = r2; cur[i + 2] = r2; dinv[i + 2] = rsqrtf((float)(v.z + 1));
        int r3 = r2 + v.z;
        rs[i + 3] = r3; cur[i + 3] = r3; dinv[i + 3] = rsqrtf((float)(v.w + 1));
        *reinterpret_cast<int4*>(cnt + i) = make_int4(0, 0, 0, 0);
    }
}

__global__ void scatter2_kernel(const int* __restrict__ src1, const int* __restrict__ dst1, int E1,
                                const int* __restrict__ src2, const int* __restrict__ dst2, int E2,
                                int* __restrict__ cur, int* __restrict__ csr) {
    int q1 = E1 >> 2, q2 = E2 >> 2;
    int i = blockIdx.x * blockDim.x + threadIdx.x;
    int4 s, d;
    if (i < q1) {
        s = *reinterpret_cast<const int4*>(src1 + i * 4);
        d = *reinterpret_cast<const int4*>(dst1 + i * 4);
    } else if (i < q1 + q2) {
        s = *reinterpret_cast<const int4*>(src2 + (i - q1) * 4);
        d = *reinterpret_cast<const int4*>(dst2 + (i - q1) * 4);
    } else return;
    csr[atomicAdd(&cur[d.x], 1)] = s.x;
    csr[atomicAdd(&cur[d.y], 1)] = s.y;
    csr[atomicAdd(&cur[d.z], 1)] = s.z;
    csr[atomicAdd(&cur[d.w], 1)] = s.w;
}

// ==================== GEMM1: fp16 m16n8k16, h0 = x@W1 -> fp16 ====================
// Block 128x128, 8 warps (4M x 2N); K chunks of 64 (4 k16-steps each).
__global__ __launch_bounds__(256) void f16_gemm1_kernel(
    const float* __restrict__ X, const float* __restrict__ W,
    __half* __restrict__ g, int nrows)
{
    constexpr int NOUT = 128, WN = 64, NT = 8;
    constexpr int LDAH = 72;                     // halfs per row (64 + 8 pad)
    __shared__ __half As[128 * LDAH];            // 18 KB
    __shared__ __half Bs[NOUT * LDAH];           // 18 KB

    const int tid = threadIdx.x;
    const int wid = tid >> 5, lane = tid & 31;
    const int wm = wid & 3, wn = wid >> 2;
    const int row0 = blockIdx.x * 128;
    const int qid = lane >> 2, qt = lane & 3;

    float acc[2][NT][4];
#pragma unroll
    for (int mi = 0; mi < 2; mi++)
#pragma unroll
        for (int ni = 0; ni < NT; ni++)
#pragma unroll
            for (int j = 0; j < 4; j++) acc[mi][ni][j] = 0.0f;

    for (int c = 0; c < 2; c++) {
        // stage A: 128 rows x 64 k-floats -> half
#pragma unroll
        for (int i = tid; i < 128 * 16; i += 256) {   // one float4 each
            int r = i >> 4, c4 = (i & 15) * 4;
            float4 v = make_float4(0.f, 0.f, 0.f, 0.f);
            if (row0 + r < nrows)
                v = *reinterpret_cast<const float4*>(X + (size_t)(row0 + r) * 128 + c * 64 + c4);
            *reinterpret_cast<__half2*>(&As[r * LDAH + c4])     = __floats2half2_rn(v.x, v.y);
            *reinterpret_cast<__half2*>(&As[r * LDAH + c4 + 2]) = __floats2half2_rn(v.z, v.w);
        }
        // stage B: Bs[n][k] = W[(c*64+k)*128 + n] -> half
#pragma unroll
        for (int i = tid; i < NOUT * 64; i += 256) {
            int nn = i % NOUT, kk = i / NOUT;
            Bs[nn * LDAH + kk] = __float2half(W[(size_t)(c * 64 + kk) * NOUT + nn]);
        }
        __syncthreads();

#pragma unroll
        for (int ks = 0; ks < 4; ks++) {
            uint32_t a[2][4];
#pragma unroll
            for (int mi = 0; mi < 2; mi++) {
                int r = wm * 32 + mi * 16 + qid;
                int k = ks * 16 + qt * 2;
                a[mi][0] = *reinterpret_cast<const uint32_t*>(&As[r * LDAH + k]);
                a[mi][1] = *reinterpret_cast<const uint32_t*>(&As[(r + 8) * LDAH + k]);
                a[mi][2] = *reinterpret_cast<const uint32_t*>(&As[r * LDAH + k + 8]);
                a[mi][3] = *reinterpret_cast<const uint32_t*>(&As[(r + 8) * LDAH + k + 8]);
            }
#pragma unroll
            for (int ni = 0; ni < NT; ni++) {
                int nn = wn * WN + ni * 8 + qid;
                int k = ks * 16 + qt * 2;
                uint32_t b[2];
                b[0] = *reinterpret_cast<const uint32_t*>(&Bs[nn * LDAH + k]);
                b[1] = *reinterpret_cast<const uint32_t*>(&Bs[nn * LDAH + k + 8]);
#pragma unroll
                for (int mi = 0; mi < 2; mi++)
                    mma_f16(acc[mi][ni], a[mi], b);
            }
        }
        __syncthreads();
    }

#pragma unroll
    for (int mi = 0; mi < 2; mi++) {
        int r0 = row0 + wm * 32 + mi * 16 + qid;
        int r1 = r0 + 8;
#pragma unroll
        for (int ni = 0; ni < NT; ni++) {
            int col = wn * WN + ni * 8 + qt * 2;
            if (r0 < nrows)
                *reinterpret_cast<__half2*>(g + (size_t)r0 * NOUT + col) =
                    __floats2half2_rn(acc[mi][ni][0], acc[mi][ni][1]);
            if (r1 < nrows)
                *reinterpret_cast<__half2*>(g + (size_t)r1 * NOUT + col) =
                    __floats2half2_rn(acc[mi][ni][2], acc[mi][ni][3]);
        }
    }
}

// ==================== GEMM2: fp16 m16n8k16, g2 = (h@[Wmu|Wls])*dinv -> fp16 ====================
__global__ __launch_bounds__(256) void f16_gemm2_kernel(
    const __half* __restrict__ H, const float* __restrict__ Wmu, const float* __restrict__ Wls,
    const float* __restrict__ dinv, __half* __restrict__ g, int nrows)
{
    constexpr int NOUT = 64, WN = 32, NT = 4;
    constexpr int LDAH = 72;
    __shared__ __half As[128 * LDAH];            // 18 KB
    __shared__ __half Bs[NOUT * LDAH];           // 9 KB

    const int tid = threadIdx.x;
    const int wid = tid >> 5, lane = tid & 31;
    const int wm = wid & 3, wn = wid >> 2;
    const int row0 = blockIdx.x * 128;
    const int qid = lane >> 2, qt = lane & 3;

    float acc[2][NT][4];
#pragma unroll
    for (int mi = 0; mi < 2; mi++)
#pragma unroll
        for (int ni = 0; ni < NT; ni++)
#pragma unroll
            for (int j = 0; j < 4; j++) acc[mi][ni][j] = 0.0f;

    for (int c = 0; c < 2; c++) {
        // stage A: copy fp16 h rows (4 halfs per iter)
#pragma unroll
        for (int i = tid; i < 128 * 16; i += 256) {
            int r = i >> 4, c4 = (i & 15) * 4;
            uint2 v = make_uint2(0u, 0u);
            if (row0 + r < nrows)
                v = *reinterpret_cast<const uint2*>(H + (size_t)(row0 + r) * 128 + c * 64 + c4);
            *reinterpret_cast<uint2*>(&As[r * LDAH + c4]) = v;
        }
        // stage B
#pragma unroll
        for (int i = tid; i < NOUT * 64; i += 256) {
            int nn = i % NOUT, kk = i / NOUT;
            int krow = c * 64 + kk;
            float bv = (nn < D_Z) ? Wmu[(size_t)krow * D_Z + nn]
                                  : Wls[(size_t)krow * D_Z + (nn - D_Z)];
            Bs[nn * LDAH + kk] = __float2half(bv);
        }
        __syncthreads();

#pragma unroll
        for (int ks = 0; ks < 4; ks++) {
            uint32_t a[2][4];
#pragma unroll
            for (int mi = 0; mi < 2; mi++) {
                int r = wm * 32 + mi * 16 + qid;
                int k = ks * 16 + qt * 2;
                a[mi][0] = *reinterpret_cast<const uint32_t*>(&As[r * LDAH + k]);
                a[mi][1] = *reinterpret_cast<const uint32_t*>(&As[(r + 8) * LDAH + k]);
                a[mi][2] = *reinterpret_cast<const uint32_t*>(&As[r * LDAH + k + 8]);
                a[mi][3] = *reinterpret_cast<const uint32_t*>(&As[(r + 8) * LDAH + k + 8]);
            }
#pragma unroll
            for (int ni = 0; ni < NT; ni++) {
                int nn = wn * WN + ni * 8 + qid;
                int k = ks * 16 + qt * 2;
                uint32_t b[2];
                b[0] = *reinterpret_cast<const uint32_t*>(&Bs[nn * LDAH + k]);
                b[1] = *reinterpret_cast<const uint32_t*>(&Bs[nn * LDAH + k + 8]);
#pragma unroll
                for (int mi = 0; mi < 2; mi++)
                    mma_f16(acc[mi][ni], a[mi], b);
            }
        }
        __syncthreads();
    }

#pragma unroll
    for (int mi = 0; mi < 2; mi++) {
        int r0 = row0 + wm * 32 + mi * 16 + qid;
        int r1 = r0 + 8;
        float w0 = (r0 < nrows) ? dinv[r0] : 0.f;
        float w1 = (r1 < nrows) ? dinv[r1] : 0.f;
#pragma unroll
        for (int ni = 0; ni < NT; ni++) {
            int col = wn * WN + ni * 8 + qt * 2;
            if (r0 < nrows)
                *reinterpret_cast<__half2*>(g + (size_t)r0 * NOUT + col) =
                    __floats2half2_rn(acc[mi][ni][0] * w0, acc[mi][ni][1] * w0);
            if (r1 < nrows)
                *reinterpret_cast<__half2*>(g + (size_t)r1 * NOUT + col) =
                    __floats2half2_rn(acc[mi][ni][2] * w1, acc[mi][ni][3] * w1);
        }
    }
}

// -------- agg1 (fp16 in/out): h[d] = relu( wd*(Σ dinv[s]*h0[s] + wd*h0[d]) + b ) --------
__global__ __launch_bounds__(256) void agg1_kernel(
    const int* __restrict__ rs, const int* __restrict__ csr,
    const __half* __restrict__ h0, const float* __restrict__ dinv,
    const float* __restrict__ b1, __half* __restrict__ h, int n)
{
    int d = (blockIdx.x * blockDim.x + threadIdx.x) >> 5;
    int lane = threadIdx.x & 31;
    if (d >= n) return;

    const uint2* gv = reinterpret_cast<const uint2*>(h0);
    float wd = dinv[d];
    float4 sv = h4_to_f4(gv[(size_t)d * 32 + lane]);
    float4 a0 = make_float4(sv.x * wd, sv.y * wd, sv.z * wd, sv.w * wd);
    float4 a1 = make_float4(0.f, 0.f, 0.f, 0.f);
    float4 a2 = make_float4(0.f, 0.f, 0.f, 0.f);
    float4 a3 = make_float4(0.f, 0.f, 0.f, 0.f);

    int e = rs[d], end = rs[d + 1];
    for (; e + 4 <= end; e += 4) {
        int s0 = __ldg(&csr[e]);
        int s1 = __ldg(&csr[e + 1]);
        int s2 = __ldg(&csr[e + 2]);
        int s3 = __ldg(&csr[e + 3]);
        float w0 = __ldg(&dinv[s0]);
        float w1 = __ldg(&dinv[s1]);
        float w2 = __ldg(&dinv[s2]);
        float w3 = __ldg(&dinv[s3]);
        float4 v0 = h4_to_f4(gv[(size_t)s0 * 32 + lane]);
        float4 v1 = h4_to_f4(gv[(size_t)s1 * 32 + lane]);
        float4 v2 = h4_to_f4(gv[(size_t)s2 * 32 + lane]);
        float4 v3 = h4_to_f4(gv[(size_t)s3 * 32 + lane]);
        a0.x = fmaf(v0.x, w0, a0.x); a0.y = fmaf(v0.y, w0, a0.y);
        a0.z = fmaf(v0.z, w0, a0.z); a0.w = fmaf(v0.w, w0, a0.w);
        a1.x = fmaf(v1.x, w1, a1.x); a1.y = fmaf(v1.y, w1, a1.y);
        a1.z = fmaf(v1.z, w1, a1.z); a1.w = fmaf(v1.w, w1, a1.w);
        a2.x = fmaf(v2.x, w2, a2.x); a2.y = fmaf(v2.y, w2, a2.y);
        a2.z = fmaf(v2.z, w2, a2.z); a2.w = fmaf(v2.w, w2, a2.w);
        a3.x = fmaf(v3.x, w3, a3.x); a3.y = fmaf(v3.y, w3, a3.y);
        a3.z = fmaf(v3.z, w3, a3.z); a3.w = fmaf(v3.w, w3, a3.w);
    }
    for (; e < end; e++) {
        int s0 = __ldg(&csr[e]);
        float w0 = __ldg(&dinv[s0]);
        float4 v0 = h4_to_f4(gv[(size_t)s0 * 32 + lane]);
        a0.x = fmaf(v0.x, w0, a0.x); a0.y = fmaf(v0.y, w0, a0.y);
        a0.z = fmaf(v0.z, w0, a0.z); a0.w = fmaf(v0.w, w0, a0.w);
    }
    float4 bb = reinterpret_cast<const float4*>(b1)[lane];
    float sx = (a0.x + a1.x) + (a2.x + a3.x);
    float sy = (a0.y + a1.y) + (a2.y + a3.y);
    float sz = (a0.z + a1.z) + (a2.z + a3.z);
    float sw = (a0.w + a1.w) + (a2.w + a3.w);
    float rx = fmaxf(fmaf(sx, wd, bb.x), 0.f);
    float ry = fmaxf(fmaf(sy, wd, bb.y), 0.f);
    float rz = fmaxf(fmaf(sz, wd, bb.z), 0.f);
    float rw = fmaxf(fmaf(sw, wd, bb.w), 0.f);
    uint2 o;
    *reinterpret_cast<__half2*>(&o.x) = __floats2half2_rn(rx, ry);
    *reinterpret_cast<__half2*>(&o.y) = __floats2half2_rn(rz, rw);
    reinterpret_cast<uint2*>(h)[(size_t)d * 32 + lane] = o;
}

// -------- agg2 (F=64, fp16 source): fused bias + mu/logstd split --------
__global__ __launch_bounds__(256) void agg2_kernel(
    const int* __restrict__ rs, const int* __restrict__ csr,
    const __half* __restrict__ g, const float* __restrict__ dinv,
    const float* __restrict__ bmu, const float* __restrict__ bls,
    float* __restrict__ out, int n)
{
    int d = (blockIdx.x * blockDim.x + threadIdx.x) >> 5;
    int lane = threadIdx.x & 31;
    if (d >= n) return;

    const __half2* gv = reinterpret_cast<const __half2*>(g);
    float2 a0 = __half22float2(gv[(size_t)d * 32 + lane]);
    float2 a1 = make_float2(0.f, 0.f);
    float2 a2 = make_float2(0.f, 0.f);
    float2 a3 = make_float2(0.f, 0.f);

    int e = rs[d], end = rs[d + 1];
    for (; e + 4 <= end; e += 4) {
        int s0 = __ldg(&csr[e]);
        int s1 = __ldg(&csr[e + 1]);
        int s2 = __ldg(&csr[e + 2]);
        int s3 = __ldg(&csr[e + 3]);
        float2 v0 = __half22float2(gv[(size_t)s0 * 32 + lane]);
        float2 v1 = __half22float2(gv[(size_t)s1 * 32 + lane]);
        float2 v2 = __half22float2(gv[(size_t)s2 * 32 + lane]);
        float2 v3 = __half22float2(gv[(size_t)s3 * 32 + lane]);
        a0.x += v0.x; a0.y += v0.y;
        a1.x += v1.x; a1.y += v1.y;
        a2.x += v2.x; a2.y += v2.y;
        a3.x += v3.x; a3.y += v3.y;
    }
    for (; e < end; e++) {
        int s0 = __ldg(&csr[e]);
        float2 v0 = __half22float2(gv[(size_t)s0 * 32 + lane]);
        a0.x += v0.x; a0.y += v0.y;
    }
    float w = dinv[d];
    float vx = ((a0.x + a1.x) + (a2.x + a3.x)) * w;
    float vy = ((a0.y + a1.y) + (a2.y + a3.y)) * w;
    int c0 = lane * 2, c1 = lane * 2 + 1;
    if (c0 < D_Z) {
        float2 o = make_float2(vx + bmu[c0], vy + bmu[c1]);
        reinterpret_cast<float2*>(out)[(size_t)d * 16 + lane] = o;
    } else {
        float2 o = make_float2(vx + bls[c0 - D_Z], vy + bls[c1 - D_Z]);
        reinterpret_cast<float2*>(out + (size_t)n * D_Z)[(size_t)d * 16 + (lane - 16)] = o;
    }
}

extern "C" void kernel_launch(void* const* d_in, const int* in_sizes, int n_in,
                              void* d_out, int out_size)
{
    const float* x    = (const float*)d_in[0];
    const int*   ei1  = (const int*)d_in[1];
    const int*   ei2  = (const int*)d_in[2];
    const float* W1   = (const float*)d_in[3];
    const float* b1   = (const float*)d_in[4];
    const float* Wmu  = (const float*)d_in[5];
    const float* bmu  = (const float*)d_in[6];
    const float* Wls  = (const float*)d_in[7];
    const float* bls  = (const float*)d_in[8];
    float* out = (float*)d_out;

    static cudaStream_t sB = nullptr;
    static cudaEvent_t evFork = nullptr, evJoin = nullptr;
    if (sB == nullptr) {
        cudaStreamCreateWithFlags(&sB, cudaStreamNonBlocking);
        cudaEventCreateWithFlags(&evFork, cudaEventDisableTiming);
        cudaEventCreateWithFlags(&evJoin, cudaEventDisableTiming);
    }

    float *p_dinv;
    __half *p_g1, *p_h, *p_g2;
    int *p_cnt, *p_cur, *p_rs, *p_part, *p_csr;
    cudaGetSymbolAddress((void**)&p_dinv, d_dinv);
    cudaGetSymbolAddress((void**)&p_cnt,  d_cnt);
    cudaGetSymbolAddress((void**)&p_cur,  d_cur);
    cudaGetSymbolAddress((void**)&p_rs,   d_rs);
    cudaGetSymbolAddress((void**)&p_part, d_part);
    cudaGetSymbolAddress((void**)&p_csr,  d_csr);
    cudaGetSymbolAddress((void**)&p_g1,   d_g1);
    cudaGetSymbolAddress((void**)&p_h,    d_h);
    cudaGetSymbolAddress((void**)&p_g2,   d_g2);

    const int n  = in_sizes[0] / D_IN;   // 50000
    const int E1 = in_sizes[1] / 2;      // 600000
    const int E2 = in_sizes[2] / 2;      // 200000
    const int* src1 = ei1; const int* dst1 = ei1 + E1;
    const int* src2 = ei2; const int* dst2 = ei2 + E2;

    const int T = 256;
    const int tiles = (n + 127) / 128;        // 391
    const int nblk = (n + 1023) / 1024;       // 49
    const int nq = (E1 >> 2) + (E2 >> 2);     // 200000

    // ---- fork: GEMM1 concurrent with CSR build ----
    cudaEventRecord(evFork, 0);
    cudaStreamWaitEvent(sB, evFork, 0);
    f16_gemm1_kernel<<<tiles, 256, 0, sB>>>(x, W1, p_g1, n);
    cudaEventRecord(evJoin, sB);

    // ---- CSR build on main stream ----
    hist2_kernel<<<(nq + T - 1) / T, T>>>(p_cnt, dst1, E1, dst2, E2);
    partial_kernel<<<nblk, 256>>>(p_cnt, p_part, n);
    scan_write_kernel<<<nblk, 256>>>(p_cnt, p_part, p_rs, p_cur, p_dinv, n, nblk);
    scatter2_kernel<<<(nq + T - 1) / T, T>>>(src1, dst1, E1, src2, dst2, E2, p_cur, p_csr);

    // ---- join, then layer-1 aggregation ----
    cudaStreamWaitEvent(0, evJoin, 0);
    agg1_kernel<<<(n * 32 + T - 1) / T, T>>>(p_rs, p_csr, p_g1, p_dinv, b1, p_h, n);

    // ---- layer 2 (fp16 MMA, fused heads) ----
    f16_gemm2_kernel<<<tiles, 256>>>(p_h, Wmu, Wls, p_dinv, p_g2, n);
    agg2_kernel<<<(n * 32 + T - 1) / T, T>>>(p_rs, p_csr, p_g2, p_dinv, bmu, bls, out, n);
}